// round 1
// baseline (speedup 1.0000x reference)
#include <cuda_runtime.h>
#include <cuda_bf16.h>

// Nearest-codeword quantization, uniform sorted 16-entry codebook.
// out[i] = argmin_c |x[i] - c|, tie broken toward the LOWER codeword
// (matches reference: pick_lo = |x - c_lo| <= |x - c_hi|).
//
// Strategy: k = clamp(floor((x - c0) * inv_step), 0, K-2) gives the bracketing
// pair (c[k], c[k+1]); resolve with the exact comparison on the true codebook
// values read from global memory. Floor fp error of +-1 can only occur when x
// is ~on a codeword (t near integer), where both brackets yield the same
// nearest codeword, so this is exactly equivalent to the searchsorted path.

#define K_CB 16

__global__ void __launch_bounds__(256)
quant_uniform_kernel(const float4* __restrict__ x,
                     const float*  __restrict__ cb,
                     float4* __restrict__ out,
                     int n4)
{
    // Codebook into registers (16 floats; broadcast L2/L1 hits).
    float c[K_CB];
#pragma unroll
    for (int i = 0; i < K_CB; i++) c[i] = __ldg(cb + i);

    const float c0 = c[0];
    const float inv_step = (float)(K_CB - 1) / (c[K_CB - 1] - c0);

    int idx = blockIdx.x * blockDim.x + threadIdx.x;
    if (idx >= n4) return;

    float4 v = x[idx];
    float4 r;

    float* vp = reinterpret_cast<float*>(&v);
    float* rp = reinterpret_cast<float*>(&r);

#pragma unroll
    for (int j = 0; j < 4; j++) {
        float xv = vp[j];
        float t = (xv - c0) * inv_step;
        int k = __float2int_rd(t);
        k = max(0, min(k, K_CB - 2));
        float lo = c[k];
        float hi = c[k + 1];
        // tie toward lower codeword
        rp[j] = (fabsf(xv - lo) <= fabsf(xv - hi)) ? lo : hi;
    }

    out[idx] = r;
}

extern "C" void kernel_launch(void* const* d_in, const int* in_sizes, int n_in,
                              void* d_out, int out_size)
{
    const float* x  = (const float*)d_in[0];
    const float* cb = (const float*)d_in[1];
    float* out = (float*)d_out;

    int n = in_sizes[0];          // 8192*8192 = 67,108,864
    int n4 = n >> 2;              // 16,777,216 float4

    int threads = 256;
    int blocks = (n4 + threads - 1) / threads;   // 65536

    quant_uniform_kernel<<<blocks, threads>>>(
        (const float4*)x, cb, (float4*)out, n4);
}

// round 2
// speedup vs baseline: 1.9440x; 1.9440x over previous
#include <cuda_runtime.h>
#include <cuda_bf16.h>

// Nearest-codeword quantization, uniform sorted 16-entry codebook.
// out[i] = argmin_c |x[i] - c|, tie toward the LOWER codeword
// (matches reference: pick_lo = |x - c_lo| <= |x - c_hi|).
//
// R2 change vs R1: codebook lives in SHARED memory (dynamic index k -> LDS,
// conflict-free: 16 floats on 16 distinct banks). R1 used a runtime-indexed
// register array, which ptxas demoted to LOCAL memory (L1=83%, DRAM=38%).
// Also ILP=2 float4 per thread for higher per-warp MLP.

#define K_CB 16

__global__ void __launch_bounds__(256)
quant_uniform_kernel(const float4* __restrict__ x,
                     const float*  __restrict__ cb,
                     float4* __restrict__ out,
                     int n4)
{
    __shared__ float s_cb[K_CB];
    if (threadIdx.x < K_CB) s_cb[threadIdx.x] = cb[threadIdx.x];
    __syncthreads();

    const float c0 = s_cb[0];
    const float inv_step = (float)(K_CB - 1) / (s_cb[K_CB - 1] - c0);

    int base = (blockIdx.x * blockDim.x + threadIdx.x) * 2;

#pragma unroll
    for (int u = 0; u < 2; u++) {
        int idx = base + u;
        if (idx >= n4) return;

        float4 v = x[idx];
        float4 r;
        float* vp = reinterpret_cast<float*>(&v);
        float* rp = reinterpret_cast<float*>(&r);

#pragma unroll
        for (int j = 0; j < 4; j++) {
            float xv = vp[j];
            float t = (xv - c0) * inv_step;
            int k = __float2int_rd(t);
            k = max(0, min(k, K_CB - 2));
            float lo = s_cb[k];
            float hi = s_cb[k + 1];
            // tie toward lower codeword
            rp[j] = (fabsf(xv - lo) <= fabsf(xv - hi)) ? lo : hi;
        }

        out[idx] = r;
    }
}

extern "C" void kernel_launch(void* const* d_in, const int* in_sizes, int n_in,
                              void* d_out, int out_size)
{
    const float* x  = (const float*)d_in[0];
    const float* cb = (const float*)d_in[1];
    float* out = (float*)d_out;

    int n = in_sizes[0];          // 8192*8192 = 67,108,864
    int n4 = n >> 2;              // 16,777,216 float4

    const int threads = 256;
    const int per_block = threads * 2;
    int blocks = (n4 + per_block - 1) / per_block;   // 32768

    quant_uniform_kernel<<<blocks, threads>>>(
        (const float4*)x, cb, (float4*)out, n4);
}